// round 2
// baseline (speedup 1.0000x reference)
#include <cuda_runtime.h>
#include <cstdint>
#include <cstddef>

#define NMAX 100000
#define EMAX 1600000

// ---------------- static device scratch (no runtime allocation) ----------------
__device__ int    g_is32;               // 1 if edge_index is int32, 0 if int64
__device__ int    g_deg[NMAX];
__device__ int    g_off[NMAX + 1];
__device__ int    g_cur[NMAX];
__device__ int    g_csr[EMAX];
__device__ int    g_bsum[256];
__device__ float  g_h1 [(size_t)NMAX * 128];   // layer1 pre-activation features
__device__ float  g_h1a[(size_t)NMAX * 128];   // layer1 output (post ELU)
__device__ float  g_h2 [(size_t)NMAX * 32];    // layer2 features
__device__ float4 g_al1s[NMAX];                // layer1 src logits (4 heads)
__device__ float4 g_al1d[NMAX];                // layer1 dst logits (4 heads)
__device__ float  g_al2s[NMAX];
__device__ float  g_al2d[NMAX];
__device__ float4 g_ex4[EMAX];                 // per-edge exp() scratch (layer1: 4 heads)
__device__ float  g_pool[32];

__device__ __forceinline__ float lrelu(float v) { return v > 0.f ? v : 0.2f * v; }

// ---------------- dtype probe: int32 vs int64 edge_index ----------------
__global__ void k_detect(const unsigned long long* __restrict__ ei, int E, int n) {
    __shared__ int sbad;
    if (threadIdx.x == 0) sbad = 0;
    __syncthreads();
    int bad = 0;
    int lim = (E < 2048) ? E : 2048;   // first `lim` 8-byte words are in-bounds either way
    for (int j = threadIdx.x; j < lim; j += blockDim.x) {
        unsigned long long v = ei[j];
        if (v >= (unsigned long long)n) bad = 1;
    }
    if (bad) atomicOr(&sbad, 1);
    __syncthreads();
    if (threadIdx.x == 0) g_is32 = sbad;
}

__device__ __forceinline__ int edge_src(const void* ei, int E, int i) {
    if (g_is32) return ((const int*)ei)[i];
    return (int)((const long long*)ei)[i];
}
__device__ __forceinline__ int edge_dst(const void* ei, int E, int i) {
    if (g_is32) return ((const int*)ei)[E + i];
    return (int)((const long long*)ei)[(size_t)E + i];
}

// ---------------- init ----------------
__global__ void k_zero(int n) {
    int i = blockIdx.x * blockDim.x + threadIdx.x;
    if (i < n) g_deg[i] = 0;
    if (i < 32) g_pool[i] = 0.f;
}

// ---------------- CSR build ----------------
__global__ void k_count(const void* __restrict__ ei, int E) {
    int i = blockIdx.x * blockDim.x + threadIdx.x;
    if (i >= E) return;
    int d = edge_dst(ei, E, i);
    atomicAdd(&g_deg[d], 1);
}

__global__ void k_scan1(int n) {
    __shared__ __align__(16) int sh[1024];
    int i = blockIdx.x * 1024 + threadIdx.x;
    int v = (i < n) ? g_deg[i] : 0;
    sh[threadIdx.x] = v;
    __syncthreads();
    int acc = v;
    for (int ofs = 1; ofs < 1024; ofs <<= 1) {
        int t = (threadIdx.x >= ofs) ? sh[threadIdx.x - ofs] : 0;
        __syncthreads();
        acc += t;
        sh[threadIdx.x] = acc;
        __syncthreads();
    }
    if (i < n) g_off[i] = acc - v;          // block-local exclusive
    if (threadIdx.x == 1023) g_bsum[blockIdx.x] = acc;  // block total
}

__global__ void k_scan2(int nb) {
    if (threadIdx.x == 0) {
        int run = 0;
        for (int b = 0; b < nb; b++) { int t = g_bsum[b]; g_bsum[b] = run; run += t; }
    }
}

__global__ void k_scan3(int n, int E) {
    int i = blockIdx.x * blockDim.x + threadIdx.x;
    if (i < n) {
        int o = g_off[i] + g_bsum[i >> 10];
        g_off[i] = o;
        g_cur[i] = o;
    }
    if (i == 0) g_off[n] = E;
}

__global__ void k_scatter(const void* __restrict__ ei, int E) {
    int i = blockIdx.x * blockDim.x + threadIdx.x;
    if (i >= E) return;
    int s = edge_src(ei, E, i);
    int d = edge_dst(ei, E, i);
    int pos = atomicAdd(&g_cur[d], 1);
    g_csr[pos] = s;
}

// ---------------- GEMM1: h1[n,128] = x[n,128] @ W1[128,128] ----------------
__global__ void k_gemm1(const float* __restrict__ A, const float* __restrict__ B, int n) {
    const int BK = 16;
    __shared__ __align__(16) float As[BK][128];
    __shared__ __align__(16) float Bs[BK][128];
    int m0 = blockIdx.x * 128;
    int tid = threadIdx.x;
    int tx = tid & 15, ty = tid >> 4;
    float acc[8][8];
#pragma unroll
    for (int i = 0; i < 8; i++)
#pragma unroll
        for (int j = 0; j < 8; j++) acc[i][j] = 0.f;

    for (int k0 = 0; k0 < 128; k0 += BK) {
        {   // A tile 128x16 -> As[k][m] transposed
            int r = tid >> 2, c = (tid & 3) * 4;
#pragma unroll
            for (int rr = 0; rr < 2; rr++) {
                int row = m0 + r + rr * 64;
                float4 v = make_float4(0.f, 0.f, 0.f, 0.f);
                if (row < n) v = *(const float4*)(A + (size_t)row * 128 + k0 + c);
                As[c + 0][r + rr * 64] = v.x;
                As[c + 1][r + rr * 64] = v.y;
                As[c + 2][r + rr * 64] = v.z;
                As[c + 3][r + rr * 64] = v.w;
            }
        }
        {   // B tile 16x128
            int r = tid >> 5, c = (tid & 31) * 4;
#pragma unroll
            for (int rr = 0; rr < 2; rr++) {
                float4 v = *(const float4*)(B + (size_t)(k0 + r + rr * 8) * 128 + c);
                *(float4*)&Bs[r + rr * 8][c] = v;
            }
        }
        __syncthreads();
#pragma unroll
        for (int k = 0; k < BK; k++) {
            float a[8], b[8];
            *(float4*)(a)     = *(float4*)&As[k][ty * 8];
            *(float4*)(a + 4) = *(float4*)&As[k][ty * 8 + 4];
            *(float4*)(b)     = *(float4*)&Bs[k][tx * 8];
            *(float4*)(b + 4) = *(float4*)&Bs[k][tx * 8 + 4];
#pragma unroll
            for (int i = 0; i < 8; i++)
#pragma unroll
                for (int j = 0; j < 8; j++) acc[i][j] = fmaf(a[i], b[j], acc[i][j]);
        }
        __syncthreads();
    }
#pragma unroll
    for (int i = 0; i < 8; i++) {
        int row = m0 + ty * 8 + i;
        if (row < n) {
            *(float4*)&g_h1[(size_t)row * 128 + tx * 8]     = *(float4*)&acc[i][0];
            *(float4*)&g_h1[(size_t)row * 128 + tx * 8 + 4] = *(float4*)&acc[i][4];
        }
    }
}

// ---------------- attention logits layer 1 ----------------
__global__ void k_al1(const float* __restrict__ a_s, const float* __restrict__ a_d, int n) {
    int idx = blockIdx.x * blockDim.x + threadIdx.x;   // node*4 + h
    if (idx >= n * 4) return;
    int h = idx & 3;
    int node = idx >> 2;
    const float4* hp = (const float4*)(g_h1 + (size_t)node * 128 + h * 32);
    const float4* av = (const float4*)(a_s + h * 32);
    const float4* bv = (const float4*)(a_d + h * 32);
    float s = 0.f, d = 0.f;
#pragma unroll
    for (int j = 0; j < 8; j++) {
        float4 v = hp[j], a = av[j], b = bv[j];
        s += v.x * a.x + v.y * a.y + v.z * a.z + v.w * a.w;
        d += v.x * b.x + v.y * b.y + v.z * b.z + v.w * b.w;
    }
    ((float*)g_al1s)[idx] = s;
    ((float*)g_al1d)[idx] = d;
}

// ---------------- layer-1 softmax-attention aggregation (warp / dst node) ----------------
__global__ void k_agg1(const float* __restrict__ b1, int n) {
    int warp = (blockIdx.x * blockDim.x + threadIdx.x) >> 5;
    int lane = threadIdx.x & 31;
    if (warp >= n) return;
    int node = warp;
    int beg = g_off[node], end = g_off[node + 1];

    float4 alD = g_al1d[node];
    float4 alS = g_al1s[node];
    float es0 = lrelu(alS.x + alD.x), es1 = lrelu(alS.y + alD.y);
    float es2 = lrelu(alS.z + alD.z), es3 = lrelu(alS.w + alD.w);

    // pass 1: max (self included)
    float m0 = es0, m1 = es1, m2 = es2, m3 = es3;
    for (int i = beg + lane; i < end; i += 32) {
        int s = g_csr[i];
        float4 a = g_al1s[s];
        m0 = fmaxf(m0, lrelu(a.x + alD.x));
        m1 = fmaxf(m1, lrelu(a.y + alD.y));
        m2 = fmaxf(m2, lrelu(a.z + alD.z));
        m3 = fmaxf(m3, lrelu(a.w + alD.w));
    }
#pragma unroll
    for (int o = 16; o > 0; o >>= 1) {
        m0 = fmaxf(m0, __shfl_xor_sync(0xffffffffu, m0, o));
        m1 = fmaxf(m1, __shfl_xor_sync(0xffffffffu, m1, o));
        m2 = fmaxf(m2, __shfl_xor_sync(0xffffffffu, m2, o));
        m3 = fmaxf(m3, __shfl_xor_sync(0xffffffffu, m3, o));
    }

    // pass 2: exp + sum; stash per-edge exps once (lane-distributed, coalesced)
    float ex0 = __expf(es0 - m0), ex1 = __expf(es1 - m1);
    float ex2 = __expf(es2 - m2), ex3 = __expf(es3 - m3);
    float t0 = (lane == 0) ? ex0 : 0.f, t1 = (lane == 0) ? ex1 : 0.f;
    float t2 = (lane == 0) ? ex2 : 0.f, t3 = (lane == 0) ? ex3 : 0.f;
    for (int i = beg + lane; i < end; i += 32) {
        int s = g_csr[i];
        float4 a = g_al1s[s];
        float4 w;
        w.x = __expf(lrelu(a.x + alD.x) - m0);
        w.y = __expf(lrelu(a.y + alD.y) - m1);
        w.z = __expf(lrelu(a.z + alD.z) - m2);
        w.w = __expf(lrelu(a.w + alD.w) - m3);
        g_ex4[i] = w;
        t0 += w.x; t1 += w.y; t2 += w.z; t3 += w.w;
    }
#pragma unroll
    for (int o = 16; o > 0; o >>= 1) {
        t0 += __shfl_xor_sync(0xffffffffu, t0, o);
        t1 += __shfl_xor_sync(0xffffffffu, t1, o);
        t2 += __shfl_xor_sync(0xffffffffu, t2, o);
        t3 += __shfl_xor_sync(0xffffffffu, t3, o);
    }
    __syncwarp(0xffffffffu);   // make g_ex4 stores visible warp-wide

    // pass 3: weighted gather (all 128 channels across the warp)
    const float* hps = g_h1 + (size_t)node * 128 + lane;
    float acc0 = hps[0]  * ex0;
    float acc1 = hps[32] * ex1;
    float acc2 = hps[64] * ex2;
    float acc3 = hps[96] * ex3;
    for (int i = beg; i < end; i++) {
        int s = g_csr[i];                 // broadcast load
        float4 w = g_ex4[i];              // broadcast load
        const float* hp = g_h1 + (size_t)s * 128 + lane;
        acc0 = fmaf(hp[0],  w.x, acc0);
        acc1 = fmaf(hp[32], w.y, acc1);
        acc2 = fmaf(hp[64], w.z, acc2);
        acc3 = fmaf(hp[96], w.w, acc3);
    }
    float i0 = 1.f / t0, i1 = 1.f / t1, i2 = 1.f / t2, i3 = 1.f / t3;
    acc0 *= i0; acc1 *= i1; acc2 *= i2; acc3 *= i3;

    // bias + ELU
    float v0 = acc0 + b1[lane];
    float v1 = acc1 + b1[32 + lane];
    float v2 = acc2 + b1[64 + lane];
    float v3 = acc3 + b1[96 + lane];
    float* op = g_h1a + (size_t)node * 128 + lane;
    op[0]  = v0 > 0.f ? v0 : (__expf(v0) - 1.f);
    op[32] = v1 > 0.f ? v1 : (__expf(v1) - 1.f);
    op[64] = v2 > 0.f ? v2 : (__expf(v2) - 1.f);
    op[96] = v3 > 0.f ? v3 : (__expf(v3) - 1.f);
}

// ---------------- GEMM2: h2[n,32] = h1a[n,128] @ W2[128,32] ----------------
__global__ void k_gemm2(const float* __restrict__ B, int n) {
    const int BK = 32;
    __shared__ __align__(16) float As[BK][128];
    __shared__ __align__(16) float Bs[BK][32];
    int m0 = blockIdx.x * 128;
    int tid = threadIdx.x;
    int rx = tid & 7;    // col group (cols rx*4..rx*4+3)
    int ry = tid >> 3;   // row group (rows ry*4..ry*4+3)
    float acc[4][4];
#pragma unroll
    for (int i = 0; i < 4; i++)
#pragma unroll
        for (int j = 0; j < 4; j++) acc[i][j] = 0.f;

    for (int k0 = 0; k0 < 128; k0 += BK) {
        {   // A tile 128x32 transposed
            int r = tid >> 3, c = (tid & 7) * 4;
#pragma unroll
            for (int rr = 0; rr < 4; rr++) {
                int row = m0 + r + rr * 32;
                float4 v = make_float4(0.f, 0.f, 0.f, 0.f);
                if (row < n) v = *(const float4*)&g_h1a[(size_t)row * 128 + k0 + c];
                As[c + 0][r + rr * 32] = v.x;
                As[c + 1][r + rr * 32] = v.y;
                As[c + 2][r + rr * 32] = v.z;
                As[c + 3][r + rr * 32] = v.w;
            }
        }
        {   // B tile 32x32
            float4 v = *(const float4*)(B + (size_t)(k0 + (tid >> 3)) * 32 + (tid & 7) * 4);
            *(float4*)&Bs[tid >> 3][(tid & 7) * 4] = v;
        }
        __syncthreads();
#pragma unroll
        for (int k = 0; k < BK; k++) {
            float4 a = *(float4*)&As[k][ry * 4];
            float4 b = *(float4*)&Bs[k][rx * 4];
            acc[0][0] = fmaf(a.x, b.x, acc[0][0]); acc[0][1] = fmaf(a.x, b.y, acc[0][1]);
            acc[0][2] = fmaf(a.x, b.z, acc[0][2]); acc[0][3] = fmaf(a.x, b.w, acc[0][3]);
            acc[1][0] = fmaf(a.y, b.x, acc[1][0]); acc[1][1] = fmaf(a.y, b.y, acc[1][1]);
            acc[1][2] = fmaf(a.y, b.z, acc[1][2]); acc[1][3] = fmaf(a.y, b.w, acc[1][3]);
            acc[2][0] = fmaf(a.z, b.x, acc[2][0]); acc[2][1] = fmaf(a.z, b.y, acc[2][1]);
            acc[2][2] = fmaf(a.z, b.z, acc[2][2]); acc[2][3] = fmaf(a.z, b.w, acc[2][3]);
            acc[3][0] = fmaf(a.w, b.x, acc[3][0]); acc[3][1] = fmaf(a.w, b.y, acc[3][1]);
            acc[3][2] = fmaf(a.w, b.z, acc[3][2]); acc[3][3] = fmaf(a.w, b.w, acc[3][3]);
        }
        __syncthreads();
    }
#pragma unroll
    for (int i = 0; i < 4; i++) {
        int row = m0 + ry * 4 + i;
        if (row < n) *(float4*)&g_h2[(size_t)row * 32 + rx * 4] = *(float4*)&acc[i][0];
    }
}

// ---------------- attention logits layer 2 ----------------
__global__ void k_al2(const float* __restrict__ a_s, const float* __restrict__ a_d, int n) {
    int idx = blockIdx.x * blockDim.x + threadIdx.x;
    if (idx >= n) return;
    const float4* hp = (const float4*)(g_h2 + (size_t)idx * 32);
    const float4* av = (const float4*)a_s;
    const float4* bv = (const float4*)a_d;
    float s = 0.f, d = 0.f;
#pragma unroll
    for (int j = 0; j < 8; j++) {
        float4 v = hp[j], a = av[j], b = bv[j];
        s += v.x * a.x + v.y * a.y + v.z * a.z + v.w * a.w;
        d += v.x * b.x + v.y * b.y + v.z * b.z + v.w * b.w;
    }
    g_al2s[idx] = s;
    g_al2d[idx] = d;
}

// ---------------- layer-2 aggregation + mean-pool partial reduction ----------------
__global__ void k_agg2(int n) {
    __shared__ __align__(16) float bacc[8][32];
    int tid = threadIdx.x;
    int lane = tid & 31;
    int wib = tid >> 5;          // warp in block (0..7)
    int warp = (blockIdx.x * blockDim.x + tid) >> 5;

    float acc = 0.f;
    if (warp < n) {
        int node = warp;
        int beg = g_off[node], end = g_off[node + 1];
        float alD = g_al2d[node];
        float es = lrelu(g_al2s[node] + alD);
        float m = es;
        for (int i = beg + lane; i < end; i += 32)
            m = fmaxf(m, lrelu(g_al2s[g_csr[i]] + alD));
#pragma unroll
        for (int o = 16; o > 0; o >>= 1) m = fmaxf(m, __shfl_xor_sync(0xffffffffu, m, o));

        float exs = __expf(es - m);
        float t = (lane == 0) ? exs : 0.f;
        for (int i = beg + lane; i < end; i += 32) {
            float w = __expf(lrelu(g_al2s[g_csr[i]] + alD) - m);
            ((float*)g_ex4)[i] = w;
            t += w;
        }
#pragma unroll
        for (int o = 16; o > 0; o >>= 1) t += __shfl_xor_sync(0xffffffffu, t, o);
        __syncwarp(0xffffffffu);

        acc = g_h2[(size_t)node * 32 + lane] * exs;
        for (int i = beg; i < end; i++) {
            int s = g_csr[i];
            float w = ((float*)g_ex4)[i];
            acc = fmaf(g_h2[(size_t)s * 32 + lane], w, acc);
        }
        acc *= (1.f / t);
    }
    bacc[wib][lane] = acc;
    __syncthreads();
    if (tid < 32) {
        float s = 0.f;
#pragma unroll
        for (int w = 0; w < 8; w++) s += bacc[w][tid];
        atomicAdd(&g_pool[tid], s);
    }
}

// ---------------- final: pooled mean -> linear -> softmax ----------------
__global__ void k_final(const float* __restrict__ linW, const float* __restrict__ linb,
                        const float* __restrict__ b2, float* __restrict__ out, int n) {
    if (threadIdx.x == 0) {
        float p[32];
        float invn = 1.f / (float)n;
        for (int c = 0; c < 32; c++) p[c] = g_pool[c] * invn + b2[c];
        float lg[3];
        for (int j = 0; j < 3; j++) lg[j] = linb[j];
        for (int c = 0; c < 32; c++)
            for (int j = 0; j < 3; j++) lg[j] += p[c] * linW[c * 3 + j];
        float mx = fmaxf(lg[0], fmaxf(lg[1], lg[2]));
        float e0 = expf(lg[0] - mx), e1 = expf(lg[1] - mx), e2 = expf(lg[2] - mx);
        float s = e0 + e1 + e2;
        out[0] = e0 / s; out[1] = e1 / s; out[2] = e2 / s;
    }
}

// ---------------- launcher ----------------
extern "C" void kernel_launch(void* const* d_in, const int* in_sizes, int n_in,
                              void* d_out, int out_size) {
    const float* x    = (const float*)d_in[0];
    const void*  ei   = d_in[1];                 // int32 or int64, probed on device
    const float* W1   = (const float*)d_in[2];
    const float* a1s  = (const float*)d_in[3];
    const float* a1d  = (const float*)d_in[4];
    const float* b1   = (const float*)d_in[5];
    const float* W2   = (const float*)d_in[6];
    const float* a2s  = (const float*)d_in[7];
    const float* a2d  = (const float*)d_in[8];
    const float* b2   = (const float*)d_in[9];
    const float* linW = (const float*)d_in[10];
    const float* linb = (const float*)d_in[11];
    float*       out  = (float*)d_out;

    int n = in_sizes[0] / 128;       // 100000
    int E = in_sizes[1] / 2;         // 1600000
    if (n > NMAX) n = NMAX;
    if (E > EMAX) E = EMAX;

    int nb = (n + 1023) / 1024;

    k_detect <<<1, 256>>>((const unsigned long long*)ei, E, n);
    k_zero   <<<(n + 255) / 256, 256>>>(n);
    k_count  <<<(E + 255) / 256, 256>>>(ei, E);
    k_scan1  <<<nb, 1024>>>(n);
    k_scan2  <<<1, 32>>>(nb);
    k_scan3  <<<(n + 255) / 256, 256>>>(n, E);
    k_scatter<<<(E + 255) / 256, 256>>>(ei, E);

    k_gemm1  <<<(n + 127) / 128, 256>>>(x, W1, n);
    k_al1    <<<(n * 4 + 255) / 256, 256>>>(a1s, a1d, n);
    k_agg1   <<<(n * 32 + 255) / 256, 256>>>(b1, n);

    k_gemm2  <<<(n + 127) / 128, 256>>>(W2, n);
    k_al2    <<<(n + 255) / 256, 256>>>(a2s, a2d, n);
    k_agg2   <<<(n * 32 + 255) / 256, 256>>>(n);

    k_final  <<<1, 32>>>(linW, linb, b2, out, n);
}

// round 3
// speedup vs baseline: 1.0404x; 1.0404x over previous
#include <cuda_runtime.h>
#include <cstdint>
#include <cstddef>

#define NMAX 100000
#define EMAX 1600000

// ---------------- static device scratch (no runtime allocation) ----------------
__device__ int    g_is32;               // 1 if edge_index is int32, 0 if int64
__device__ int    g_deg[NMAX];
__device__ int    g_off[NMAX + 1];
__device__ int    g_cur[NMAX];
__device__ int    g_csr[EMAX];
__device__ int    g_bsum[256];
__device__ float  g_h1 [(size_t)NMAX * 128];   // layer1 pre-activation features
__device__ float  g_h1a[(size_t)NMAX * 128];   // layer1 output (post ELU)
__device__ float  g_h2 [(size_t)NMAX * 32];    // layer2 features
__device__ float4 g_al1s[NMAX];                // layer1 src logits (4 heads)
__device__ float4 g_al1d[NMAX];                // layer1 dst logits (4 heads)
__device__ float  g_al2s[NMAX];
__device__ float  g_al2d[NMAX];
__device__ float  g_pool[32];

__device__ __forceinline__ float lrelu(float v) { return v > 0.f ? v : 0.2f * v; }

// ---------------- dtype probe: int32 vs int64 edge_index ----------------
__global__ void k_detect(const unsigned long long* __restrict__ ei, int E, int n) {
    __shared__ int sbad;
    if (threadIdx.x == 0) sbad = 0;
    __syncthreads();
    int bad = 0;
    int lim = (E < 2048) ? E : 2048;   // first `lim` 8-byte words are in-bounds either way
    for (int j = threadIdx.x; j < lim; j += blockDim.x) {
        unsigned long long v = ei[j];
        if (v >= (unsigned long long)n) bad = 1;
    }
    if (bad) atomicOr(&sbad, 1);
    __syncthreads();
    if (threadIdx.x == 0) g_is32 = sbad;
}

__device__ __forceinline__ int edge_src(const void* ei, int E, int i) {
    if (g_is32) return ((const int*)ei)[i];
    return (int)((const long long*)ei)[i];
}
__device__ __forceinline__ int edge_dst(const void* ei, int E, int i) {
    if (g_is32) return ((const int*)ei)[E + i];
    return (int)((const long long*)ei)[(size_t)E + i];
}

// ---------------- init ----------------
__global__ void k_zero(int n) {
    int i = blockIdx.x * blockDim.x + threadIdx.x;
    if (i < n) g_deg[i] = 0;
    if (i < 32) g_pool[i] = 0.f;
}

// ---------------- CSR build ----------------
__global__ void k_count(const void* __restrict__ ei, int E) {
    int i = blockIdx.x * blockDim.x + threadIdx.x;
    if (i >= E) return;
    int d = edge_dst(ei, E, i);
    atomicAdd(&g_deg[d], 1);
}

__global__ void k_scan1(int n) {
    __shared__ __align__(16) int sh[1024];
    int i = blockIdx.x * 1024 + threadIdx.x;
    int v = (i < n) ? g_deg[i] : 0;
    sh[threadIdx.x] = v;
    __syncthreads();
    int acc = v;
    for (int ofs = 1; ofs < 1024; ofs <<= 1) {
        int t = (threadIdx.x >= ofs) ? sh[threadIdx.x - ofs] : 0;
        __syncthreads();
        acc += t;
        sh[threadIdx.x] = acc;
        __syncthreads();
    }
    if (i < n) g_off[i] = acc - v;          // block-local exclusive
    if (threadIdx.x == 1023) g_bsum[blockIdx.x] = acc;  // block total
}

__global__ void k_scan2(int nb) {
    if (threadIdx.x == 0) {
        int run = 0;
        for (int b = 0; b < nb; b++) { int t = g_bsum[b]; g_bsum[b] = run; run += t; }
    }
}

__global__ void k_scan3(int n, int E) {
    int i = blockIdx.x * blockDim.x + threadIdx.x;
    if (i < n) {
        int o = g_off[i] + g_bsum[i >> 10];
        g_off[i] = o;
        g_cur[i] = o;
    }
    if (i == 0) g_off[n] = E;
}

__global__ void k_scatter(const void* __restrict__ ei, int E) {
    int i = blockIdx.x * blockDim.x + threadIdx.x;
    if (i >= E) return;
    int s = edge_src(ei, E, i);
    int d = edge_dst(ei, E, i);
    int pos = atomicAdd(&g_cur[d], 1);
    g_csr[pos] = s;
}

// ---------------- GEMM1: h1[n,128] = x[n,128] @ W1[128,128] ----------------
__global__ void k_gemm1(const float* __restrict__ A, const float* __restrict__ B, int n) {
    const int BK = 16;
    __shared__ __align__(16) float As[BK][128];
    __shared__ __align__(16) float Bs[BK][128];
    int m0 = blockIdx.x * 128;
    int tid = threadIdx.x;
    int tx = tid & 15, ty = tid >> 4;
    float acc[8][8];
#pragma unroll
    for (int i = 0; i < 8; i++)
#pragma unroll
        for (int j = 0; j < 8; j++) acc[i][j] = 0.f;

    for (int k0 = 0; k0 < 128; k0 += BK) {
        {   // A tile 128x16 -> As[k][m] transposed
            int r = tid >> 2, c = (tid & 3) * 4;
#pragma unroll
            for (int rr = 0; rr < 2; rr++) {
                int row = m0 + r + rr * 64;
                float4 v = make_float4(0.f, 0.f, 0.f, 0.f);
                if (row < n) v = *(const float4*)(A + (size_t)row * 128 + k0 + c);
                As[c + 0][r + rr * 64] = v.x;
                As[c + 1][r + rr * 64] = v.y;
                As[c + 2][r + rr * 64] = v.z;
                As[c + 3][r + rr * 64] = v.w;
            }
        }
        {   // B tile 16x128
            int r = tid >> 5, c = (tid & 31) * 4;
#pragma unroll
            for (int rr = 0; rr < 2; rr++) {
                float4 v = *(const float4*)(B + (size_t)(k0 + r + rr * 8) * 128 + c);
                *(float4*)&Bs[r + rr * 8][c] = v;
            }
        }
        __syncthreads();
#pragma unroll
        for (int k = 0; k < BK; k++) {
            float a[8], b[8];
            *(float4*)(a)     = *(float4*)&As[k][ty * 8];
            *(float4*)(a + 4) = *(float4*)&As[k][ty * 8 + 4];
            *(float4*)(b)     = *(float4*)&Bs[k][tx * 8];
            *(float4*)(b + 4) = *(float4*)&Bs[k][tx * 8 + 4];
#pragma unroll
            for (int i = 0; i < 8; i++)
#pragma unroll
                for (int j = 0; j < 8; j++) acc[i][j] = fmaf(a[i], b[j], acc[i][j]);
        }
        __syncthreads();
    }
#pragma unroll
    for (int i = 0; i < 8; i++) {
        int row = m0 + ty * 8 + i;
        if (row < n) {
            *(float4*)&g_h1[(size_t)row * 128 + tx * 8]     = *(float4*)&acc[i][0];
            *(float4*)&g_h1[(size_t)row * 128 + tx * 8 + 4] = *(float4*)&acc[i][4];
        }
    }
}

// ---------------- attention logits layer 1 ----------------
__global__ void k_al1(const float* __restrict__ a_s, const float* __restrict__ a_d, int n) {
    int idx = blockIdx.x * blockDim.x + threadIdx.x;   // node*4 + h
    if (idx >= n * 4) return;
    int h = idx & 3;
    int node = idx >> 2;
    const float4* hp = (const float4*)(g_h1 + (size_t)node * 128 + h * 32);
    const float4* av = (const float4*)(a_s + h * 32);
    const float4* bv = (const float4*)(a_d + h * 32);
    float s = 0.f, d = 0.f;
#pragma unroll
    for (int j = 0; j < 8; j++) {
        float4 v = hp[j], a = av[j], b = bv[j];
        s += v.x * a.x + v.y * a.y + v.z * a.z + v.w * a.w;
        d += v.x * b.x + v.y * b.y + v.z * b.z + v.w * b.w;
    }
    ((float*)g_al1s)[idx] = s;
    ((float*)g_al1d)[idx] = d;
}

// ---------------- layer-1 softmax-attention aggregation: single fused pass ----------------
// One warp per dst node. No max-shift (logits bounded: |al| small), exp computed once
// per edge lane-parallel, staged in smem, then all 32 lanes sweep the chunk gathering
// 128 channels/edge. No per-edge global scratch.
__global__ void k_agg1(const float* __restrict__ b1, int n) {
    __shared__ __align__(16) float4 s_w[8][32];
    __shared__ int s_src[8][32];
    int lane = threadIdx.x & 31;
    int wib = threadIdx.x >> 5;
    int node = blockIdx.x * 8 + wib;
    if (node >= n) return;
    int beg = g_off[node], end = g_off[node + 1];

    float4 alD = g_al1d[node];
    float4 alS = g_al1s[node];

    // self-loop contribution
    float w0 = __expf(lrelu(alS.x + alD.x));
    float w1 = __expf(lrelu(alS.y + alD.y));
    float w2 = __expf(lrelu(alS.z + alD.z));
    float w3 = __expf(lrelu(alS.w + alD.w));
    float t0 = (lane == 0) ? w0 : 0.f, t1 = (lane == 0) ? w1 : 0.f;
    float t2 = (lane == 0) ? w2 : 0.f, t3 = (lane == 0) ? w3 : 0.f;

    const float* hps = g_h1 + (size_t)node * 128 + lane;
    float acc0 = hps[0]  * w0;
    float acc1 = hps[32] * w1;
    float acc2 = hps[64] * w2;
    float acc3 = hps[96] * w3;

    for (int chunk = beg; chunk < end; chunk += 32) {
        int i = chunk + lane;
        float4 w = make_float4(0.f, 0.f, 0.f, 0.f);
        int s = 0;
        if (i < end) {
            s = g_csr[i];
            float4 a = g_al1s[s];
            w.x = __expf(lrelu(a.x + alD.x));
            w.y = __expf(lrelu(a.y + alD.y));
            w.z = __expf(lrelu(a.z + alD.z));
            w.w = __expf(lrelu(a.w + alD.w));
            t0 += w.x; t1 += w.y; t2 += w.z; t3 += w.w;
        }
        s_src[wib][lane] = s;
        s_w[wib][lane] = w;
        __syncwarp(0xffffffffu);
        int cnt = end - chunk; if (cnt > 32) cnt = 32;
#pragma unroll 2
        for (int j = 0; j < cnt; j++) {
            int sj = s_src[wib][j];
            float4 wj = s_w[wib][j];
            const float* hp = g_h1 + (size_t)sj * 128 + lane;
            acc0 = fmaf(hp[0],  wj.x, acc0);
            acc1 = fmaf(hp[32], wj.y, acc1);
            acc2 = fmaf(hp[64], wj.z, acc2);
            acc3 = fmaf(hp[96], wj.w, acc3);
        }
        __syncwarp(0xffffffffu);
    }

#pragma unroll
    for (int o = 16; o > 0; o >>= 1) {
        t0 += __shfl_xor_sync(0xffffffffu, t0, o);
        t1 += __shfl_xor_sync(0xffffffffu, t1, o);
        t2 += __shfl_xor_sync(0xffffffffu, t2, o);
        t3 += __shfl_xor_sync(0xffffffffu, t3, o);
    }
    acc0 *= (1.f / t0); acc1 *= (1.f / t1); acc2 *= (1.f / t2); acc3 *= (1.f / t3);

    // bias + ELU
    float v0 = acc0 + b1[lane];
    float v1 = acc1 + b1[32 + lane];
    float v2 = acc2 + b1[64 + lane];
    float v3 = acc3 + b1[96 + lane];
    float* op = g_h1a + (size_t)node * 128 + lane;
    op[0]  = v0 > 0.f ? v0 : (__expf(v0) - 1.f);
    op[32] = v1 > 0.f ? v1 : (__expf(v1) - 1.f);
    op[64] = v2 > 0.f ? v2 : (__expf(v2) - 1.f);
    op[96] = v3 > 0.f ? v3 : (__expf(v3) - 1.f);
}

// ---------------- GEMM2: h2[n,32] = h1a[n,128] @ W2[128,32] ----------------
__global__ void k_gemm2(const float* __restrict__ B, int n) {
    const int BK = 32;
    __shared__ __align__(16) float As[BK][128];
    __shared__ __align__(16) float Bs[BK][32];
    int m0 = blockIdx.x * 128;
    int tid = threadIdx.x;
    int rx = tid & 7;    // col group (cols rx*4..rx*4+3)
    int ry = tid >> 3;   // row group (rows ry*4..ry*4+3)
    float acc[4][4];
#pragma unroll
    for (int i = 0; i < 4; i++)
#pragma unroll
        for (int j = 0; j < 4; j++) acc[i][j] = 0.f;

    for (int k0 = 0; k0 < 128; k0 += BK) {
        {   // A tile 128x32 transposed
            int r = tid >> 3, c = (tid & 7) * 4;
#pragma unroll
            for (int rr = 0; rr < 4; rr++) {
                int row = m0 + r + rr * 32;
                float4 v = make_float4(0.f, 0.f, 0.f, 0.f);
                if (row < n) v = *(const float4*)&g_h1a[(size_t)row * 128 + k0 + c];
                As[c + 0][r + rr * 32] = v.x;
                As[c + 1][r + rr * 32] = v.y;
                As[c + 2][r + rr * 32] = v.z;
                As[c + 3][r + rr * 32] = v.w;
            }
        }
        {   // B tile 32x32
            float4 v = *(const float4*)(B + (size_t)(k0 + (tid >> 3)) * 32 + (tid & 7) * 4);
            *(float4*)&Bs[tid >> 3][(tid & 7) * 4] = v;
        }
        __syncthreads();
#pragma unroll
        for (int k = 0; k < BK; k++) {
            float4 a = *(float4*)&As[k][ry * 4];
            float4 b = *(float4*)&Bs[k][rx * 4];
            acc[0][0] = fmaf(a.x, b.x, acc[0][0]); acc[0][1] = fmaf(a.x, b.y, acc[0][1]);
            acc[0][2] = fmaf(a.x, b.z, acc[0][2]); acc[0][3] = fmaf(a.x, b.w, acc[0][3]);
            acc[1][0] = fmaf(a.y, b.x, acc[1][0]); acc[1][1] = fmaf(a.y, b.y, acc[1][1]);
            acc[1][2] = fmaf(a.y, b.z, acc[1][2]); acc[1][3] = fmaf(a.y, b.w, acc[1][3]);
            acc[2][0] = fmaf(a.z, b.x, acc[2][0]); acc[2][1] = fmaf(a.z, b.y, acc[2][1]);
            acc[2][2] = fmaf(a.z, b.z, acc[2][2]); acc[2][3] = fmaf(a.z, b.w, acc[2][3]);
            acc[3][0] = fmaf(a.w, b.x, acc[3][0]); acc[3][1] = fmaf(a.w, b.y, acc[3][1]);
            acc[3][2] = fmaf(a.w, b.z, acc[3][2]); acc[3][3] = fmaf(a.w, b.w, acc[3][3]);
        }
        __syncthreads();
    }
#pragma unroll
    for (int i = 0; i < 4; i++) {
        int row = m0 + ry * 4 + i;
        if (row < n) *(float4*)&g_h2[(size_t)row * 32 + rx * 4] = *(float4*)&acc[i][0];
    }
}

// ---------------- attention logits layer 2 ----------------
__global__ void k_al2(const float* __restrict__ a_s, const float* __restrict__ a_d, int n) {
    int idx = blockIdx.x * blockDim.x + threadIdx.x;
    if (idx >= n) return;
    const float4* hp = (const float4*)(g_h2 + (size_t)idx * 32);
    const float4* av = (const float4*)a_s;
    const float4* bv = (const float4*)a_d;
    float s = 0.f, d = 0.f;
#pragma unroll
    for (int j = 0; j < 8; j++) {
        float4 v = hp[j], a = av[j], b = bv[j];
        s += v.x * a.x + v.y * a.y + v.z * a.z + v.w * a.w;
        d += v.x * b.x + v.y * b.y + v.z * b.z + v.w * b.w;
    }
    g_al2s[idx] = s;
    g_al2d[idx] = d;
}

// ---------------- layer-2 aggregation (fused single pass) + mean-pool partial ----------------
__global__ void k_agg2(int n) {
    __shared__ __align__(16) float s_w2[8][32];
    __shared__ int s_src2[8][32];
    __shared__ __align__(16) float bacc[8][32];
    int tid = threadIdx.x;
    int lane = tid & 31;
    int wib = tid >> 5;          // warp in block (0..7)
    int node = blockIdx.x * 8 + wib;

    float acc = 0.f;
    if (node < n) {
        int beg = g_off[node], end = g_off[node + 1];
        float alD = g_al2d[node];
        float ws = __expf(lrelu(g_al2s[node] + alD));   // self-loop
        float t = (lane == 0) ? ws : 0.f;
        acc = g_h2[(size_t)node * 32 + lane] * ws;

        for (int chunk = beg; chunk < end; chunk += 32) {
            int i = chunk + lane;
            float w = 0.f;
            int s = 0;
            if (i < end) {
                s = g_csr[i];
                w = __expf(lrelu(g_al2s[s] + alD));
                t += w;
            }
            s_src2[wib][lane] = s;
            s_w2[wib][lane] = w;
            __syncwarp(0xffffffffu);
            int cnt = end - chunk; if (cnt > 32) cnt = 32;
#pragma unroll 2
            for (int j = 0; j < cnt; j++) {
                int sj = s_src2[wib][j];
                float wj = s_w2[wib][j];
                acc = fmaf(g_h2[(size_t)sj * 32 + lane], wj, acc);
            }
            __syncwarp(0xffffffffu);
        }
#pragma unroll
        for (int o = 16; o > 0; o >>= 1) t += __shfl_xor_sync(0xffffffffu, t, o);
        acc *= (1.f / t);
    }
    bacc[wib][lane] = acc;
    __syncthreads();
    if (tid < 32) {
        float s = 0.f;
#pragma unroll
        for (int w = 0; w < 8; w++) s += bacc[w][tid];
        atomicAdd(&g_pool[tid], s);
    }
}

// ---------------- final: pooled mean -> linear -> softmax ----------------
__global__ void k_final(const float* __restrict__ linW, const float* __restrict__ linb,
                        const float* __restrict__ b2, float* __restrict__ out, int n) {
    if (threadIdx.x == 0) {
        float p[32];
        float invn = 1.f / (float)n;
        for (int c = 0; c < 32; c++) p[c] = g_pool[c] * invn + b2[c];
        float lg[3];
        for (int j = 0; j < 3; j++) lg[j] = linb[j];
        for (int c = 0; c < 32; c++)
            for (int j = 0; j < 3; j++) lg[j] += p[c] * linW[c * 3 + j];
        float mx = fmaxf(lg[0], fmaxf(lg[1], lg[2]));
        float e0 = expf(lg[0] - mx), e1 = expf(lg[1] - mx), e2 = expf(lg[2] - mx);
        float s = e0 + e1 + e2;
        out[0] = e0 / s; out[1] = e1 / s; out[2] = e2 / s;
    }
}

// ---------------- launcher ----------------
extern "C" void kernel_launch(void* const* d_in, const int* in_sizes, int n_in,
                              void* d_out, int out_size) {
    const float* x    = (const float*)d_in[0];
    const void*  ei   = d_in[1];                 // int32 or int64, probed on device
    const float* W1   = (const float*)d_in[2];
    const float* a1s  = (const float*)d_in[3];
    const float* a1d  = (const float*)d_in[4];
    const float* b1   = (const float*)d_in[5];
    const float* W2   = (const float*)d_in[6];
    const float* a2s  = (const float*)d_in[7];
    const float* a2d  = (const float*)d_in[8];
    const float* b2   = (const float*)d_in[9];
    const float* linW = (const float*)d_in[10];
    const float* linb = (const float*)d_in[11];
    float*       out  = (float*)d_out;

    int n = in_sizes[0] / 128;       // 100000
    int E = in_sizes[1] / 2;         // 1600000
    if (n > NMAX) n = NMAX;
    if (E > EMAX) E = EMAX;

    int nb = (n + 1023) / 1024;

    k_detect <<<1, 256>>>((const unsigned long long*)ei, E, n);
    k_zero   <<<(n + 255) / 256, 256>>>(n);
    k_count  <<<(E + 255) / 256, 256>>>(ei, E);
    k_scan1  <<<nb, 1024>>>(n);
    k_scan2  <<<1, 32>>>(nb);
    k_scan3  <<<(n + 255) / 256, 256>>>(n, E);
    k_scatter<<<(E + 255) / 256, 256>>>(ei, E);

    k_gemm1  <<<(n + 127) / 128, 256>>>(x, W1, n);
    k_al1    <<<(n * 4 + 255) / 256, 256>>>(a1s, a1d, n);
    k_agg1   <<<(n + 7) / 8, 256>>>(b1, n);

    k_gemm2  <<<(n + 127) / 128, 256>>>(W2, n);
    k_al2    <<<(n + 255) / 256, 256>>>(a2s, a2d, n);
    k_agg2   <<<(n + 7) / 8, 256>>>(n);

    k_final  <<<1, 32>>>(linW, linb, b2, out, n);
}

// round 4
// speedup vs baseline: 1.2229x; 1.1754x over previous
#include <cuda_runtime.h>
#include <cstdint>
#include <cstddef>

#define NMAX 100000
#define EMAX 1600000

// ---------------- static device scratch (no runtime allocation) ----------------
__device__ int    g_is32;               // 1 if edge_index is int32, 0 if int64
__device__ int    g_deg[NMAX];
__device__ int    g_off[NMAX + 1];
__device__ int    g_cur[NMAX];
__device__ int    g_csr[EMAX];
__device__ int    g_bsum[256];
__device__ float  g_h1 [(size_t)NMAX * 128];   // layer1 pre-activation features
__device__ float  g_h1a[(size_t)NMAX * 128];   // layer1 output (post ELU)
__device__ float  g_h2 [(size_t)NMAX * 32];    // layer2 features
__device__ float4 g_al1s[NMAX];                // layer1 src logits (4 heads)
__device__ float4 g_al1d[NMAX];                // layer1 dst logits (4 heads)
__device__ float  g_al2s[NMAX];
__device__ float  g_al2d[NMAX];
__device__ float  g_pool[32];

__device__ __forceinline__ float lrelu(float v) { return v > 0.f ? v : 0.2f * v; }

__device__ __forceinline__ unsigned f2tf32(float x) {
    unsigned r;
    asm("cvt.rna.tf32.f32 %0, %1;" : "=r"(r) : "f"(x));
    return r;
}

// ---------------- dtype probe: int32 vs int64 edge_index ----------------
__global__ void k_detect(const unsigned long long* __restrict__ ei, int E, int n) {
    __shared__ int sbad;
    if (threadIdx.x == 0) sbad = 0;
    __syncthreads();
    int bad = 0;
    int lim = (E < 2048) ? E : 2048;   // first `lim` 8-byte words are in-bounds either way
    for (int j = threadIdx.x; j < lim; j += blockDim.x) {
        unsigned long long v = ei[j];
        if (v >= (unsigned long long)n) bad = 1;
    }
    if (bad) atomicOr(&sbad, 1);
    __syncthreads();
    if (threadIdx.x == 0) g_is32 = sbad;
}

__device__ __forceinline__ int edge_src(const void* ei, int E, int i) {
    if (g_is32) return ((const int*)ei)[i];
    return (int)((const long long*)ei)[i];
}
__device__ __forceinline__ int edge_dst(const void* ei, int E, int i) {
    if (g_is32) return ((const int*)ei)[E + i];
    return (int)((const long long*)ei)[(size_t)E + i];
}

// ---------------- init ----------------
__global__ void k_zero(int n) {
    int i = blockIdx.x * blockDim.x + threadIdx.x;
    if (i < n) g_deg[i] = 0;
    if (i < 32) g_pool[i] = 0.f;
}

// ---------------- CSR build ----------------
__global__ void k_count(const void* __restrict__ ei, int E) {
    int i = blockIdx.x * blockDim.x + threadIdx.x;
    if (i >= E) return;
    int d = edge_dst(ei, E, i);
    atomicAdd(&g_deg[d], 1);
}

__global__ void k_scan1(int n) {
    __shared__ __align__(16) int sh[1024];
    int i = blockIdx.x * 1024 + threadIdx.x;
    int v = (i < n) ? g_deg[i] : 0;
    sh[threadIdx.x] = v;
    __syncthreads();
    int acc = v;
    for (int ofs = 1; ofs < 1024; ofs <<= 1) {
        int t = (threadIdx.x >= ofs) ? sh[threadIdx.x - ofs] : 0;
        __syncthreads();
        acc += t;
        sh[threadIdx.x] = acc;
        __syncthreads();
    }
    if (i < n) g_off[i] = acc - v;          // block-local exclusive
    if (threadIdx.x == 1023) g_bsum[blockIdx.x] = acc;  // block total
}

__global__ void k_scan2(int nb) {
    if (threadIdx.x == 0) {
        int run = 0;
        for (int b = 0; b < nb; b++) { int t = g_bsum[b]; g_bsum[b] = run; run += t; }
    }
}

__global__ void k_scan3(int n, int E) {
    int i = blockIdx.x * blockDim.x + threadIdx.x;
    if (i < n) {
        int o = g_off[i] + g_bsum[i >> 10];
        g_off[i] = o;
        g_cur[i] = o;
    }
    if (i == 0) g_off[n] = E;
}

__global__ void k_scatter(const void* __restrict__ ei, int E) {
    int i = blockIdx.x * blockDim.x + threadIdx.x;
    if (i >= E) return;
    int s = edge_src(ei, E, i);
    int d = edge_dst(ei, E, i);
    int pos = atomicAdd(&g_cur[d], 1);
    g_csr[pos] = s;
}

// ---------------- GEMM1 (tf32 tensor cores): h1[n,128] = x[n,128] @ W1[128,128] --------
// 128x128 block tile, K staged 64-wide, 8 warps each 32x64 via m16n8k8 tf32 mma.
__global__ void __launch_bounds__(256) k_gemm1(const float* __restrict__ A,
                                               const float* __restrict__ B, int n) {
    __shared__ __align__(16) float As[128][68];   // [m][k], stride 68 -> conflict-free frags
    __shared__ __align__(16) float Bs[64][132];   // [k][n], stride 132
    int tid = threadIdx.x;
    int lane = tid & 31;
    int warp = tid >> 5;          // 0..7
    int warpM = warp & 3;         // 4 warps in M
    int warpN = warp >> 2;        // 2 warps in N
    int g = lane >> 2;            // group id 0..7
    int t = lane & 3;             // thread-in-group 0..3
    int m0 = blockIdx.x * 128;

    float c[2][8][4];
#pragma unroll
    for (int mt = 0; mt < 2; mt++)
#pragma unroll
        for (int nt = 0; nt < 8; nt++)
#pragma unroll
            for (int q = 0; q < 4; q++) c[mt][nt][q] = 0.f;

    for (int k0 = 0; k0 < 128; k0 += 64) {
        // load A tile: 128 rows x 64 k-cols (convert to tf32 bits)
        {
            int r = tid >> 4;            // 0..15
            int c4 = (tid & 15) * 4;     // 0..60
#pragma unroll
            for (int p = 0; p < 8; p++) {
                int row = r + p * 16;
                int grow = m0 + row;
                float4 v = make_float4(0.f, 0.f, 0.f, 0.f);
                if (grow < n) v = *(const float4*)(A + (size_t)grow * 128 + k0 + c4);
                As[row][c4 + 0] = __uint_as_float(f2tf32(v.x));
                As[row][c4 + 1] = __uint_as_float(f2tf32(v.y));
                As[row][c4 + 2] = __uint_as_float(f2tf32(v.z));
                As[row][c4 + 3] = __uint_as_float(f2tf32(v.w));
            }
        }
        // load B tile: 64 k-rows x 128 n-cols
        {
            int r = tid >> 5;            // 0..7
            int c4 = (tid & 31) * 4;     // 0..124
#pragma unroll
            for (int p = 0; p < 8; p++) {
                int k = r + p * 8;
                float4 v = *(const float4*)(B + (size_t)(k0 + k) * 128 + c4);
                Bs[k][c4 + 0] = __uint_as_float(f2tf32(v.x));
                Bs[k][c4 + 1] = __uint_as_float(f2tf32(v.y));
                Bs[k][c4 + 2] = __uint_as_float(f2tf32(v.z));
                Bs[k][c4 + 3] = __uint_as_float(f2tf32(v.w));
            }
        }
        __syncthreads();

#pragma unroll
        for (int ks = 0; ks < 8; ks++) {
            int kk = ks * 8;
            unsigned a[2][4];
#pragma unroll
            for (int mt = 0; mt < 2; mt++) {
                int r = warpM * 32 + mt * 16 + g;
                a[mt][0] = __float_as_uint(As[r    ][kk + t    ]);
                a[mt][1] = __float_as_uint(As[r + 8][kk + t    ]);
                a[mt][2] = __float_as_uint(As[r    ][kk + t + 4]);
                a[mt][3] = __float_as_uint(As[r + 8][kk + t + 4]);
            }
            unsigned b[8][2];
#pragma unroll
            for (int nt = 0; nt < 8; nt++) {
                int cN = warpN * 64 + nt * 8 + g;
                b[nt][0] = __float_as_uint(Bs[kk + t    ][cN]);
                b[nt][1] = __float_as_uint(Bs[kk + t + 4][cN]);
            }
#pragma unroll
            for (int mt = 0; mt < 2; mt++)
#pragma unroll
                for (int nt = 0; nt < 8; nt++) {
                    asm volatile(
                        "mma.sync.aligned.m16n8k8.row.col.f32.tf32.tf32.f32 "
                        "{%0,%1,%2,%3}, {%4,%5,%6,%7}, {%8,%9}, {%0,%1,%2,%3};"
                        : "+f"(c[mt][nt][0]), "+f"(c[mt][nt][1]),
                          "+f"(c[mt][nt][2]), "+f"(c[mt][nt][3])
                        : "r"(a[mt][0]), "r"(a[mt][1]), "r"(a[mt][2]), "r"(a[mt][3]),
                          "r"(b[nt][0]), "r"(b[nt][1]));
                }
        }
        __syncthreads();
    }

    // epilogue: c0,c1 -> (row, 2t..2t+1); c2,c3 -> (row+8, 2t..2t+1)
#pragma unroll
    for (int mt = 0; mt < 2; mt++) {
        int row = m0 + warpM * 32 + mt * 16 + g;
#pragma unroll
        for (int nt = 0; nt < 8; nt++) {
            int col = warpN * 64 + nt * 8 + t * 2;
            if (row < n) {
                float2 v0 = make_float2(c[mt][nt][0], c[mt][nt][1]);
                *(float2*)&g_h1[(size_t)row * 128 + col] = v0;
            }
            if (row + 8 < n) {
                float2 v1 = make_float2(c[mt][nt][2], c[mt][nt][3]);
                *(float2*)&g_h1[(size_t)(row + 8) * 128 + col] = v1;
            }
        }
    }
}

// ---------------- attention logits layer 1 ----------------
__global__ void k_al1(const float* __restrict__ a_s, const float* __restrict__ a_d, int n) {
    int idx = blockIdx.x * blockDim.x + threadIdx.x;   // node*4 + h
    if (idx >= n * 4) return;
    int h = idx & 3;
    int node = idx >> 2;
    const float4* hp = (const float4*)(g_h1 + (size_t)node * 128 + h * 32);
    const float4* av = (const float4*)(a_s + h * 32);
    const float4* bv = (const float4*)(a_d + h * 32);
    float s = 0.f, d = 0.f;
#pragma unroll
    for (int j = 0; j < 8; j++) {
        float4 v = hp[j], a = av[j], b = bv[j];
        s += v.x * a.x + v.y * a.y + v.z * a.z + v.w * a.w;
        d += v.x * b.x + v.y * b.y + v.z * b.z + v.w * b.w;
    }
    ((float*)g_al1s)[idx] = s;
    ((float*)g_al1d)[idx] = d;
}

// ---------------- layer-1 softmax-attention aggregation: single fused pass ----------------
__global__ void k_agg1(const float* __restrict__ b1, int n) {
    __shared__ __align__(16) float4 s_w[8][32];
    __shared__ int s_src[8][32];
    int lane = threadIdx.x & 31;
    int wib = threadIdx.x >> 5;
    int node = blockIdx.x * 8 + wib;
    if (node >= n) return;
    int beg = g_off[node], end = g_off[node + 1];

    float4 alD = g_al1d[node];
    float4 alS = g_al1s[node];

    // self-loop contribution
    float w0 = __expf(lrelu(alS.x + alD.x));
    float w1 = __expf(lrelu(alS.y + alD.y));
    float w2 = __expf(lrelu(alS.z + alD.z));
    float w3 = __expf(lrelu(alS.w + alD.w));
    float t0 = (lane == 0) ? w0 : 0.f, t1 = (lane == 0) ? w1 : 0.f;
    float t2 = (lane == 0) ? w2 : 0.f, t3 = (lane == 0) ? w3 : 0.f;

    const float* hps = g_h1 + (size_t)node * 128 + lane;
    float acc0 = hps[0]  * w0;
    float acc1 = hps[32] * w1;
    float acc2 = hps[64] * w2;
    float acc3 = hps[96] * w3;

    for (int chunk = beg; chunk < end; chunk += 32) {
        int i = chunk + lane;
        float4 w = make_float4(0.f, 0.f, 0.f, 0.f);
        int s = 0;
        if (i < end) {
            s = g_csr[i];
            float4 a = g_al1s[s];
            w.x = __expf(lrelu(a.x + alD.x));
            w.y = __expf(lrelu(a.y + alD.y));
            w.z = __expf(lrelu(a.z + alD.z));
            w.w = __expf(lrelu(a.w + alD.w));
            t0 += w.x; t1 += w.y; t2 += w.z; t3 += w.w;
        }
        s_src[wib][lane] = s;
        s_w[wib][lane] = w;
        __syncwarp(0xffffffffu);
        int cnt = end - chunk; if (cnt > 32) cnt = 32;
#pragma unroll 2
        for (int j = 0; j < cnt; j++) {
            int sj = s_src[wib][j];
            float4 wj = s_w[wib][j];
            const float* hp = g_h1 + (size_t)sj * 128 + lane;
            acc0 = fmaf(hp[0],  wj.x, acc0);
            acc1 = fmaf(hp[32], wj.y, acc1);
            acc2 = fmaf(hp[64], wj.z, acc2);
            acc3 = fmaf(hp[96], wj.w, acc3);
        }
        __syncwarp(0xffffffffu);
    }

#pragma unroll
    for (int o = 16; o > 0; o >>= 1) {
        t0 += __shfl_xor_sync(0xffffffffu, t0, o);
        t1 += __shfl_xor_sync(0xffffffffu, t1, o);
        t2 += __shfl_xor_sync(0xffffffffu, t2, o);
        t3 += __shfl_xor_sync(0xffffffffu, t3, o);
    }
    acc0 *= (1.f / t0); acc1 *= (1.f / t1); acc2 *= (1.f / t2); acc3 *= (1.f / t3);

    // bias + ELU
    float v0 = acc0 + b1[lane];
    float v1 = acc1 + b1[32 + lane];
    float v2 = acc2 + b1[64 + lane];
    float v3 = acc3 + b1[96 + lane];
    float* op = g_h1a + (size_t)node * 128 + lane;
    op[0]  = v0 > 0.f ? v0 : (__expf(v0) - 1.f);
    op[32] = v1 > 0.f ? v1 : (__expf(v1) - 1.f);
    op[64] = v2 > 0.f ? v2 : (__expf(v2) - 1.f);
    op[96] = v3 > 0.f ? v3 : (__expf(v3) - 1.f);
}

// ---------------- GEMM2: h2[n,32] = h1a[n,128] @ W2[128,32] ----------------
__global__ void k_gemm2(const float* __restrict__ B, int n) {
    const int BK = 32;
    __shared__ __align__(16) float As[BK][128];
    __shared__ __align__(16) float Bs[BK][32];
    int m0 = blockIdx.x * 128;
    int tid = threadIdx.x;
    int rx = tid & 7;    // col group (cols rx*4..rx*4+3)
    int ry = tid >> 3;   // row group (rows ry*4..ry*4+3)
    float acc[4][4];
#pragma unroll
    for (int i = 0; i < 4; i++)
#pragma unroll
        for (int j = 0; j < 4; j++) acc[i][j] = 0.f;

    for (int k0 = 0; k0 < 128; k0 += BK) {
        {   // A tile 128x32 transposed
            int r = tid >> 3, c = (tid & 7) * 4;
#pragma unroll
            for (int rr = 0; rr < 4; rr++) {
                int row = m0 + r + rr * 32;
                float4 v = make_float4(0.f, 0.f, 0.f, 0.f);
                if (row < n) v = *(const float4*)&g_h1a[(size_t)row * 128 + k0 + c];
                As[c + 0][r + rr * 32] = v.x;
                As[c + 1][r + rr * 32] = v.y;
                As[c + 2][r + rr * 32] = v.z;
                As[c + 3][r + rr * 32] = v.w;
            }
        }
        {   // B tile 32x32
            float4 v = *(const float4*)(B + (size_t)(k0 + (tid >> 3)) * 32 + (tid & 7) * 4);
            *(float4*)&Bs[tid >> 3][(tid & 7) * 4] = v;
        }
        __syncthreads();
#pragma unroll
        for (int k = 0; k < BK; k++) {
            float4 a = *(float4*)&As[k][ry * 4];
            float4 b = *(float4*)&Bs[k][rx * 4];
            acc[0][0] = fmaf(a.x, b.x, acc[0][0]); acc[0][1] = fmaf(a.x, b.y, acc[0][1]);
            acc[0][2] = fmaf(a.x, b.z, acc[0][2]); acc[0][3] = fmaf(a.x, b.w, acc[0][3]);
            acc[1][0] = fmaf(a.y, b.x, acc[1][0]); acc[1][1] = fmaf(a.y, b.y, acc[1][1]);
            acc[1][2] = fmaf(a.y, b.z, acc[1][2]); acc[1][3] = fmaf(a.y, b.w, acc[1][3]);
            acc[2][0] = fmaf(a.z, b.x, acc[2][0]); acc[2][1] = fmaf(a.z, b.y, acc[2][1]);
            acc[2][2] = fmaf(a.z, b.z, acc[2][2]); acc[2][3] = fmaf(a.z, b.w, acc[2][3]);
            acc[3][0] = fmaf(a.w, b.x, acc[3][0]); acc[3][1] = fmaf(a.w, b.y, acc[3][1]);
            acc[3][2] = fmaf(a.w, b.z, acc[3][2]); acc[3][3] = fmaf(a.w, b.w, acc[3][3]);
        }
        __syncthreads();
    }
#pragma unroll
    for (int i = 0; i < 4; i++) {
        int row = m0 + ry * 4 + i;
        if (row < n) *(float4*)&g_h2[(size_t)row * 32 + rx * 4] = *(float4*)&acc[i][0];
    }
}

// ---------------- attention logits layer 2 ----------------
__global__ void k_al2(const float* __restrict__ a_s, const float* __restrict__ a_d, int n) {
    int idx = blockIdx.x * blockDim.x + threadIdx.x;
    if (idx >= n) return;
    const float4* hp = (const float4*)(g_h2 + (size_t)idx * 32);
    const float4* av = (const float4*)a_s;
    const float4* bv = (const float4*)a_d;
    float s = 0.f, d = 0.f;
#pragma unroll
    for (int j = 0; j < 8; j++) {
        float4 v = hp[j], a = av[j], b = bv[j];
        s += v.x * a.x + v.y * a.y + v.z * a.z + v.w * a.w;
        d += v.x * b.x + v.y * b.y + v.z * b.z + v.w * b.w;
    }
    g_al2s[idx] = s;
    g_al2d[idx] = d;
}

// ---------------- layer-2 aggregation (fused single pass) + mean-pool partial ----------------
__global__ void k_agg2(int n) {
    __shared__ __align__(16) float s_w2[8][32];
    __shared__ int s_src2[8][32];
    __shared__ __align__(16) float bacc[8][32];
    int tid = threadIdx.x;
    int lane = tid & 31;
    int wib = tid >> 5;          // warp in block (0..7)
    int node = blockIdx.x * 8 + wib;

    float acc = 0.f;
    if (node < n) {
        int beg = g_off[node], end = g_off[node + 1];
        float alD = g_al2d[node];
        float ws = __expf(lrelu(g_al2s[node] + alD));   // self-loop
        float t = (lane == 0) ? ws : 0.f;
        acc = g_h2[(size_t)node * 32 + lane] * ws;

        for (int chunk = beg; chunk < end; chunk += 32) {
            int i = chunk + lane;
            float w = 0.f;
            int s = 0;
            if (i < end) {
                s = g_csr[i];
                w = __expf(lrelu(g_al2s[s] + alD));
                t += w;
            }
            s_src2[wib][lane] = s;
            s_w2[wib][lane] = w;
            __syncwarp(0xffffffffu);
            int cnt = end - chunk; if (cnt > 32) cnt = 32;
#pragma unroll 2
            for (int j = 0; j < cnt; j++) {
                int sj = s_src2[wib][j];
                float wj = s_w2[wib][j];
                acc = fmaf(g_h2[(size_t)sj * 32 + lane], wj, acc);
            }
            __syncwarp(0xffffffffu);
        }
#pragma unroll
        for (int o = 16; o > 0; o >>= 1) t += __shfl_xor_sync(0xffffffffu, t, o);
        acc *= (1.f / t);
    }
    bacc[wib][lane] = acc;
    __syncthreads();
    if (tid < 32) {
        float s = 0.f;
#pragma unroll
        for (int w = 0; w < 8; w++) s += bacc[w][tid];
        atomicAdd(&g_pool[tid], s);
    }
}

// ---------------- final: pooled mean -> linear -> softmax ----------------
__global__ void k_final(const float* __restrict__ linW, const float* __restrict__ linb,
                        const float* __restrict__ b2, float* __restrict__ out, int n) {
    if (threadIdx.x == 0) {
        float p[32];
        float invn = 1.f / (float)n;
        for (int c = 0; c < 32; c++) p[c] = g_pool[c] * invn + b2[c];
        float lg[3];
        for (int j = 0; j < 3; j++) lg[j] = linb[j];
        for (int c = 0; c < 32; c++)
            for (int j = 0; j < 3; j++) lg[j] += p[c] * linW[c * 3 + j];
        float mx = fmaxf(lg[0], fmaxf(lg[1], lg[2]));
        float e0 = expf(lg[0] - mx), e1 = expf(lg[1] - mx), e2 = expf(lg[2] - mx);
        float s = e0 + e1 + e2;
        out[0] = e0 / s; out[1] = e1 / s; out[2] = e2 / s;
    }
}

// ---------------- launcher ----------------
extern "C" void kernel_launch(void* const* d_in, const int* in_sizes, int n_in,
                              void* d_out, int out_size) {
    const float* x    = (const float*)d_in[0];
    const void*  ei   = d_in[1];                 // int32 or int64, probed on device
    const float* W1   = (const float*)d_in[2];
    const float* a1s  = (const float*)d_in[3];
    const float* a1d  = (const float*)d_in[4];
    const float* b1   = (const float*)d_in[5];
    const float* W2   = (const float*)d_in[6];
    const float* a2s  = (const float*)d_in[7];
    const float* a2d  = (const float*)d_in[8];
    const float* b2   = (const float*)d_in[9];
    const float* linW = (const float*)d_in[10];
    const float* linb = (const float*)d_in[11];
    float*       out  = (float*)d_out;

    int n = in_sizes[0] / 128;       // 100000
    int E = in_sizes[1] / 2;         // 1600000
    if (n > NMAX) n = NMAX;
    if (E > EMAX) E = EMAX;

    int nb = (n + 1023) / 1024;

    k_detect <<<1, 256>>>((const unsigned long long*)ei, E, n);
    k_zero   <<<(n + 255) / 256, 256>>>(n);
    k_count  <<<(E + 255) / 256, 256>>>(ei, E);
    k_scan1  <<<nb, 1024>>>(n);
    k_scan2  <<<1, 32>>>(nb);
    k_scan3  <<<(n + 255) / 256, 256>>>(n, E);
    k_scatter<<<(E + 255) / 256, 256>>>(ei, E);

    k_gemm1  <<<(n + 127) / 128, 256>>>(x, W1, n);
    k_al1    <<<(n * 4 + 255) / 256, 256>>>(a1s, a1d, n);
    k_agg1   <<<(n + 7) / 8, 256>>>(b1, n);

    k_gemm2  <<<(n + 127) / 128, 256>>>(W2, n);
    k_al2    <<<(n + 255) / 256, 256>>>(a2s, a2d, n);
    k_agg2   <<<(n + 7) / 8, 256>>>(n);

    k_final  <<<1, 32>>>(linW, linb, b2, out, n);
}